// round 12
// baseline (speedup 1.0000x reference)
#include <cuda_runtime.h>
#include <cuda_bf16.h>
#include <math.h>
#include <stdint.h>

#define N_NODES 50000
#define N_PAD   50048            /* 391 * 128 */
#define N_EDGES 800000
#define IN_DIM  384
#define HID     128
#define HEADS   4
#define OUT_DIM 5
#define F1      (HEADS * HID)    /* 512 */
#define EPS     1e-16f
#define NEG_SLOPE 0.2f
#define KC      64               /* K per chunk */
#define NCHUNK  18               /* 3 terms * 384/64 */
#define NEG_INF __int_as_float(0xff800000)
#define SCAN_NBLK ((N_NODES + 1023) / 1024)   /* 49 */

/* ---------------- scratch (device globals; no allocations allowed) -------- */
__device__ float g_h1  [(size_t)N_NODES * F1];     /* 102.4MB */
__device__ float g_alS1[N_NODES * HEADS];
__device__ float g_alD1[N_NODES * HEADS];
__device__ float g_h2p [N_NODES * 8];              /* padded h2 [N,8] */
__device__ float g_alS2[N_NODES];
__device__ float g_alD2[N_NODES];
/* CSR by destination */
__device__ int g_cnt   [N_NODES];
__device__ int g_rowptr[N_NODES + 1];
__device__ int g_cursor[N_NODES];
__device__ int g_ssrc  [N_EDGES];
__device__ int g_bsum  [SCAN_NBLK];
/* bf16 split operands for tensor-core GEMM1 */
__device__ __nv_bfloat16 g_xhi[(size_t)N_PAD * IN_DIM];
__device__ __nv_bfloat16 g_xlo[(size_t)N_PAD * IN_DIM];
__device__ __nv_bfloat16 g_wthi[(size_t)F1 * IN_DIM];   /* W1^T [512 x 384] */
__device__ __nv_bfloat16 g_wtlo[(size_t)F1 * IN_DIM];

/* ---------------- helpers ------------------------------------------------- */
__device__ __forceinline__ uint32_t smem_u32(const void* p) {
    uint32_t a;
    asm("{ .reg .u64 t; cvta.to.shared.u64 t, %1; cvt.u32.u64 %0, t; }"
        : "=r"(a) : "l"(p));
    return a;
}
__device__ __forceinline__ float leaky(float v) {
    return v > 0.0f ? v : NEG_SLOPE * v;
}
__device__ __forceinline__ void ldsm_x4(uint32_t* r, uint32_t addr) {
    asm volatile("ldmatrix.sync.aligned.m8n8.x4.shared.b16 {%0,%1,%2,%3}, [%4];"
                 : "=r"(r[0]), "=r"(r[1]), "=r"(r[2]), "=r"(r[3]) : "r"(addr));
}
__device__ __forceinline__ void mma_bf16(float* c, const uint32_t* a,
                                         const uint32_t* b) {
    asm volatile("mma.sync.aligned.m16n8k16.row.col.f32.bf16.bf16.f32 "
                 "{%0,%1,%2,%3}, {%4,%5,%6,%7}, {%8,%9}, {%0,%1,%2,%3};"
                 : "+f"(c[0]), "+f"(c[1]), "+f"(c[2]), "+f"(c[3])
                 : "r"(a[0]), "r"(a[1]), "r"(a[2]), "r"(a[3]),
                   "r"(b[0]), "r"(b[1]));
}
__device__ __forceinline__ void cp16(uint32_t saddr, const void* gaddr) {
    asm volatile("cp.async.cg.shared.global [%0], [%1], 16;"
                 :: "r"(saddr), "l"(gaddr));
}
#define CP_COMMIT() asm volatile("cp.async.commit_group;")
#define CP_WAIT0()  asm volatile("cp.async.wait_group 0;")
#define CP_WAIT1()  asm volatile("cp.async.wait_group 1;")

/* ---------------- split_x + split_w + init (fused) ------------------------- */
__global__ void split_xw_kernel(const float* __restrict__ x,
                                const float* __restrict__ W1) {
    size_t tid = (size_t)blockIdx.x * blockDim.x + threadIdx.x;
    if (tid < N_NODES * HEADS) { g_alS1[tid] = 0.0f; g_alD1[tid] = 0.0f; }

    /* W1^T split (196608 elements, done by the first threads) */
    if (tid < (size_t)F1 * IN_DIM) {
        int n = (int)(tid / IN_DIM), k = (int)(tid - (size_t)n * IN_DIM);
        float v = W1[(size_t)k * F1 + n];
        __nv_bfloat16 hi = __float2bfloat16(v);
        g_wthi[tid] = hi;
        g_wtlo[tid] = __float2bfloat16(v - __bfloat162float(hi));
    }

    size_t t = tid * 4;
    if (t >= (size_t)N_PAD * IN_DIM) return;
    float4 v = (t < (size_t)N_NODES * IN_DIM) ? *(const float4*)(x + t)
                                              : make_float4(0.f, 0.f, 0.f, 0.f);
    float vv[4] = {v.x, v.y, v.z, v.w};
    __nv_bfloat16 hi[4], lo[4];
#pragma unroll
    for (int i = 0; i < 4; i++) {
        hi[i] = __float2bfloat16(vv[i]);
        lo[i] = __float2bfloat16(vv[i] - __bfloat162float(hi[i]));
    }
    *(uint2*)(g_xhi + t) = *(uint2*)hi;
    *(uint2*)(g_xlo + t) = *(uint2*)lo;
}

/* ---------------- CSR build (stream B) ------------------------------------- */
__global__ void zero_cnt_kernel() {
    int t = blockIdx.x * blockDim.x + threadIdx.x;
    if (t < N_NODES) g_cnt[t] = 0;
}
__global__ void count_kernel(const int* __restrict__ dst) {
    int e = blockIdx.x * blockDim.x + threadIdx.x;
    if (e < N_EDGES) atomicAdd(&g_cnt[dst[e]], 1);
}
__global__ __launch_bounds__(1024)
void scan1_kernel() {                 /* per-block Hillis-Steele */
    __shared__ int s[1024];
    const int t = threadIdx.x;
    const int g = blockIdx.x * 1024 + t;
    const int v = (g < N_NODES) ? g_cnt[g] : 0;
    s[t] = v;
    __syncthreads();
#pragma unroll
    for (int off = 1; off < 1024; off <<= 1) {
        int x = (t >= off) ? s[t - off] : 0;
        __syncthreads();
        s[t] += x;
        __syncthreads();
    }
    if (g < N_NODES) g_rowptr[g] = s[t] - v;     /* exclusive partial */
    if (t == 1023) g_bsum[blockIdx.x] = s[1023];
}
__global__ void scan2_kernel() {      /* tiny serial scan of 49 block sums */
    if (threadIdx.x == 0) {
        int run = 0;
#pragma unroll 1
        for (int i = 0; i < SCAN_NBLK; i++) {
            int v = g_bsum[i];
            g_bsum[i] = run;
            run += v;
        }
        g_rowptr[N_NODES] = run;
    }
}
__global__ void scan3_kernel() {      /* add block offsets, fill cursor */
    int g = blockIdx.x * blockDim.x + threadIdx.x;
    if (g < N_NODES) {
        int v = g_rowptr[g] + g_bsum[g >> 10];
        g_rowptr[g] = v;
        g_cursor[g] = v;
    }
}
__global__ void scatter_kernel(const int* __restrict__ src,
                               const int* __restrict__ dst) {
    int e = blockIdx.x * blockDim.x + threadIdx.x;
    if (e >= N_EDGES) return;
    int p = atomicAdd(&g_cursor[dst[e]], 1);
    g_ssrc[p] = src[e];
}

/* ------- GEMM1 via mma.sync bf16x3, cp.async 3-stage pipeline -------------- */
#define GEMM_SMEM (3 * 32768)

__global__ __launch_bounds__(256, 2)
void gemm_mma_kernel(const float* __restrict__ aSrc,
                     const float* __restrict__ aDst) {
    extern __shared__ char smem[];
    const uint32_t sb = smem_u32(smem);
    const int tid = threadIdx.x, lane = tid & 31, wid = tid >> 5;
    const int wM = (wid & 3) * 32, wN = (wid >> 2) * 64;
    const size_t bm = (size_t)blockIdx.y * 128;
    const int bn0 = blockIdx.x * 128;

    float acc[2][8][4];
#pragma unroll
    for (int i = 0; i < 2; i++)
#pragma unroll
        for (int j = 0; j < 8; j++)
#pragma unroll
            for (int q = 0; q < 4; q++) acc[i][j][q] = 0.0f;

    auto issue = [&](int ch, int buf) {
        const int term = ch / 6, k0 = (ch % 6) * KC;
        const __nv_bfloat16* Ag = (term < 2) ? g_xhi : g_xlo;
        const __nv_bfloat16* Bg = (term == 1) ? g_wtlo : g_wthi;
        const uint32_t base = sb + buf * 32768;
#pragma unroll
        for (int l = 0; l < 4; l++) {
            int i = tid + l * 256;
            int r = i >> 3, c = i & 7;
            uint32_t off = r * 128 + ((c ^ (r & 7)) << 4);
            cp16(base + off, Ag + (bm + r) * IN_DIM + k0 + c * 8);
            cp16(base + 16384 + off, Bg + (size_t)(bn0 + r) * IN_DIM + k0 + c * 8);
        }
        CP_COMMIT();
    };

    issue(0, 0);
    issue(1, 1);

    for (int ch = 0; ch < NCHUNK; ch++) {
        if (ch + 1 < NCHUNK) CP_WAIT1(); else CP_WAIT0();
        __syncthreads();
        if (ch + 2 < NCHUNK) issue(ch + 2, (ch + 2) % 3);
        const uint32_t sbA = sb + (ch % 3) * 32768;
        const uint32_t sbB = sbA + 16384;
#pragma unroll
        for (int k16 = 0; k16 < 4; k16++) {
            uint32_t a[2][4];
#pragma unroll
            for (int am = 0; am < 2; am++) {
                int r = wM + am * 16 + (lane & 15);
                int c = k16 * 2 + (lane >> 4);
                ldsm_x4(a[am], sbA + r * 128 + ((c ^ (r & 7)) << 4));
            }
#pragma unroll
            for (int bn2 = 0; bn2 < 4; bn2++) {
                int n = wN + bn2 * 16 + ((lane >> 4) << 3) + (lane & 7);
                int c = k16 * 2 + ((lane >> 3) & 1);
                uint32_t b[4];
                ldsm_x4(b, sbB + n * 128 + ((c ^ (n & 7)) << 4));
                mma_bf16(acc[0][bn2 * 2], a[0], b);
                mma_bf16(acc[1][bn2 * 2], a[1], b);
                mma_bf16(acc[0][bn2 * 2 + 1], a[0], b + 2);
                mma_bf16(acc[1][bn2 * 2 + 1], a[1], b + 2);
            }
        }
    }

    /* epilogue: write h1 + fused alpha1 partial dot products */
    const int qr = lane >> 2, qc = (lane & 3) * 2;
    const int hh = bn0 >> 7;
    float sA[4] = {0, 0, 0, 0}, sD[4] = {0, 0, 0, 0};

#pragma unroll
    for (int am = 0; am < 2; am++) {
        size_t r0 = bm + wM + am * 16 + qr;
#pragma unroll
        for (int half = 0; half < 2; half++) {
            size_t rr = r0 + half * 8;
            if (rr < N_NODES) {
                float* dstp = g_h1 + rr * F1 + bn0 + wN + qc;
#pragma unroll
                for (int bn = 0; bn < 8; bn++) {
                    float v0 = acc[am][bn][half * 2];
                    float v1 = acc[am][bn][half * 2 + 1];
                    *(float2*)(dstp + bn * 8) = make_float2(v0, v1);
                    const int c0 = bn0 + wN + bn * 8 + qc;
                    sA[am * 2 + half] += v0 * __ldg(aSrc + c0) + v1 * __ldg(aSrc + c0 + 1);
                    sD[am * 2 + half] += v0 * __ldg(aDst + c0) + v1 * __ldg(aDst + c0 + 1);
                }
            }
        }
    }
#pragma unroll
    for (int i = 0; i < 4; i++) {
#pragma unroll
        for (int o = 1; o <= 2; o <<= 1) {
            sA[i] += __shfl_xor_sync(0xffffffffu, sA[i], o);
            sD[i] += __shfl_xor_sync(0xffffffffu, sD[i], o);
        }
    }
    if ((lane & 3) == 0) {
#pragma unroll
        for (int am = 0; am < 2; am++)
#pragma unroll
            for (int half = 0; half < 2; half++) {
                size_t rr = bm + wM + am * 16 + half * 8 + qr;
                if (rr < N_NODES) {
                    atomicAdd(&g_alS1[rr * HEADS + hh], sA[am * 2 + half]);
                    atomicAdd(&g_alD1[rr * HEADS + hh], sD[am * 2 + half]);
                }
            }
    }
}

/* -------- layer1 fused: one warp per dst, ALL 4 heads ---------------------- */
__global__ __launch_bounds__(256)
void gat1_fused(const float* __restrict__ b1, const float* __restrict__ W2,
                const float* __restrict__ a_s2, const float* __restrict__ a_d2) {
    const int d = (blockIdx.x * blockDim.x + threadIdx.x) >> 5;
    const int lane = threadIdx.x & 31;
    if (d >= N_NODES) return;
    const int rs = g_rowptr[d];
    const int deg = g_rowptr[d + 1] - rs;
    const float4 aD4 = *(const float4*)&g_alD1[d * HEADS];
    const float aD[4] = {aD4.x, aD4.y, aD4.z, aD4.w};

    float m[4] = {NEG_INF, NEG_INF, NEG_INF, NEG_INF};
    float den[4] = {0, 0, 0, 0};
    float acc[4][4] = {};

    for (int base = 0; base < deg; base += 32) {
        const bool act = base + lane < deg;
        int s = 0;
        float lg[4] = {NEG_INF, NEG_INF, NEG_INF, NEG_INF};
        if (act) {
            s = g_ssrc[rs + base + lane];
            float4 a4 = *(const float4*)&g_alS1[s * HEADS];
            lg[0] = leaky(a4.x + aD[0]);
            lg[1] = leaky(a4.y + aD[1]);
            lg[2] = leaky(a4.z + aD[2]);
            lg[3] = leaky(a4.w + aD[3]);
        }
        float ex[4];
#pragma unroll
        for (int h = 0; h < 4; h++) {
            float bmx = lg[h];
#pragma unroll
            for (int o = 16; o; o >>= 1)
                bmx = fmaxf(bmx, __shfl_xor_sync(0xffffffffu, bmx, o));
            const float mnew = fmaxf(m[h], bmx);
            const float sc = __expf(m[h] - mnew);
            den[h] *= sc;
            acc[h][0] *= sc; acc[h][1] *= sc; acc[h][2] *= sc; acc[h][3] *= sc;
            ex[h] = act ? __expf(lg[h] - mnew) : 0.f;
            den[h] += ex[h];
            m[h] = mnew;
        }
        const int lim = min(32, deg - base);
        for (int jj = 0; jj < lim; jj++) {
            const int sj = __shfl_sync(0xffffffffu, s, jj);
            const float w0 = __shfl_sync(0xffffffffu, ex[0], jj);
            const float w1 = __shfl_sync(0xffffffffu, ex[1], jj);
            const float w2 = __shfl_sync(0xffffffffu, ex[2], jj);
            const float w3 = __shfl_sync(0xffffffffu, ex[3], jj);
            const float* row = g_h1 + (size_t)sj * F1 + lane * 4;
            const float4 v0 = *(const float4*)(row);
            const float4 v1 = *(const float4*)(row + HID);
            const float4 v2 = *(const float4*)(row + 2 * HID);
            const float4 v3 = *(const float4*)(row + 3 * HID);
            acc[0][0] += w0 * v0.x; acc[0][1] += w0 * v0.y;
            acc[0][2] += w0 * v0.z; acc[0][3] += w0 * v0.w;
            acc[1][0] += w1 * v1.x; acc[1][1] += w1 * v1.y;
            acc[1][2] += w1 * v1.z; acc[1][3] += w1 * v1.w;
            acc[2][0] += w2 * v2.x; acc[2][1] += w2 * v2.y;
            acc[2][2] += w2 * v2.z; acc[2][3] += w2 * v2.w;
            acc[3][0] += w3 * v3.x; acc[3][1] += w3 * v3.y;
            acc[3][2] += w3 * v3.z; acc[3][3] += w3 * v3.w;
        }
    }
    float inv[4];
#pragma unroll
    for (int h = 0; h < 4; h++) {
        float dn = den[h];
#pragma unroll
        for (int o = 16; o; o >>= 1)
            dn += __shfl_xor_sync(0xffffffffu, dn, o);
        inv[h] = 1.0f / (dn + EPS);
    }

    float p[OUT_DIM] = {0, 0, 0, 0, 0};
#pragma unroll
    for (int h = 0; h < 4; h++) {
#pragma unroll
        for (int q = 0; q < 4; q++) {
            const int c = h * HID + lane * 4 + q;
            float val = acc[h][q] * inv[h] + b1[c];
            val = val > 0.0f ? val : expm1f(val);
            const float* wr = W2 + c * OUT_DIM;
#pragma unroll
            for (int k = 0; k < OUT_DIM; k++) p[k] += val * wr[k];
        }
    }
#pragma unroll
    for (int k = 0; k < OUT_DIM; k++) {
#pragma unroll
        for (int o = 16; o; o >>= 1)
            p[k] += __shfl_xor_sync(0xffffffffu, p[k], o);
    }
    if (lane == 0) {
        float as = 0.f, ad = 0.f;
#pragma unroll
        for (int k = 0; k < OUT_DIM; k++) {
            g_h2p[d * 8 + k] = p[k];
            as += p[k] * a_s2[k];
            ad += p[k] * a_d2[k];
        }
        g_alS2[d] = as;
        g_alD2[d] = ad;
    }
}

/* -------- layer2 fused: per-lane online softmax, direct store -------------- */
__global__ __launch_bounds__(256)
void gat2_fused(float* __restrict__ dout, const float* __restrict__ b2) {
    const int d = (blockIdx.x * blockDim.x + threadIdx.x) >> 5;
    const int lane = threadIdx.x & 31;
    if (d >= N_NODES) return;
    const int rs = g_rowptr[d];
    const int deg = g_rowptr[d + 1] - rs;
    if (deg == 0) {
        if (lane == 0) {
#pragma unroll
            for (int k = 0; k < OUT_DIM; k++)
                dout[d * OUT_DIM + k] = b2[k];
        }
        return;
    }
    const float aD = g_alD2[d];

    float m = NEG_INF, den = 0.f;
    float acc[OUT_DIM] = {0, 0, 0, 0, 0};
    for (int j = lane; j < deg; j += 32) {
        int s = g_ssrc[rs + j];
        float lg = leaky(g_alS2[s] + aD);
        float mnew = fmaxf(m, lg);
        float sc = __expf(m - mnew);
        float ex = __expf(lg - mnew);
        den = den * sc + ex;
#pragma unroll
        for (int k = 0; k < OUT_DIM; k++)
            acc[k] = acc[k] * sc + ex * g_h2p[s * 8 + k];
        m = mnew;
    }
    float M = m;
#pragma unroll
    for (int o = 16; o; o >>= 1)
        M = fmaxf(M, __shfl_xor_sync(0xffffffffu, M, o));
    float sc = __expf(m - M);
    den *= sc;
#pragma unroll
    for (int k = 0; k < OUT_DIM; k++) acc[k] *= sc;
#pragma unroll
    for (int o = 16; o; o >>= 1) {
        den += __shfl_xor_sync(0xffffffffu, den, o);
#pragma unroll
        for (int k = 0; k < OUT_DIM; k++)
            acc[k] += __shfl_xor_sync(0xffffffffu, acc[k], o);
    }
    if (lane == 0) {
        const float inv = 1.0f / (den + EPS);
#pragma unroll
        for (int k = 0; k < OUT_DIM; k++)
            dout[d * OUT_DIM + k] = acc[k] * inv + b2[k];
    }
}

/* ---------------- launch --------------------------------------------------- */
extern "C" void kernel_launch(void* const* d_in, const int* in_sizes, int n_in,
                              void* d_out, int out_size) {
    const float* x   = (const float*)d_in[0];
    const int*   ei  = (const int*)  d_in[1];
    const float* W1  = (const float*)d_in[2];
    const float* aS1 = (const float*)d_in[3];
    const float* aD1 = (const float*)d_in[4];
    const float* b1  = (const float*)d_in[5];
    const float* W2  = (const float*)d_in[6];
    const float* aS2 = (const float*)d_in[7];
    const float* aD2 = (const float*)d_in[8];
    const float* b2  = (const float*)d_in[9];
    float*       out = (float*)d_out;

    const int* src = ei;
    const int* dst = ei + N_EDGES;

    static bool init_done = false;
    static cudaStream_t sB;
    static cudaEvent_t evFork, evJoin;
    if (!init_done) {
        cudaFuncSetAttribute(gemm_mma_kernel,
                             cudaFuncAttributeMaxDynamicSharedMemorySize, GEMM_SMEM);
        cudaStreamCreateWithFlags(&sB, cudaStreamNonBlocking);
        cudaEventCreateWithFlags(&evFork, cudaEventDisableTiming);
        cudaEventCreateWithFlags(&evJoin, cudaEventDisableTiming);

        /* L2 residency hint for g_h1 using the EXISTING persisting quota.
           NOTE: cudaDeviceSetLimit is forbidden by the harness; we only QUERY
           the current quota and scale hitRatio to it. All failures ignored. */
        size_t quota = 0;
        if (cudaDeviceGetLimit(&quota, cudaLimitPersistingL2CacheSize)
                == cudaSuccess && quota > 0) {
            void* h1ptr = nullptr;
            if (cudaGetSymbolAddress(&h1ptr, g_h1) == cudaSuccess && h1ptr) {
                int dev = 0;
                cudaGetDevice(&dev);
                cudaDeviceProp prop;
                size_t win = sizeof(g_h1);
                if (cudaGetDeviceProperties(&prop, dev) == cudaSuccess &&
                    prop.accessPolicyMaxWindowSize > 0 &&
                    (size_t)prop.accessPolicyMaxWindowSize < win)
                    win = (size_t)prop.accessPolicyMaxWindowSize;
                float hr = (float)((double)quota >= (double)win
                                   ? 1.0 : (double)quota / (double)win);
                cudaStreamAttrValue attr;
                attr.accessPolicyWindow.base_ptr = h1ptr;
                attr.accessPolicyWindow.num_bytes = win;
                attr.accessPolicyWindow.hitRatio = hr;
                attr.accessPolicyWindow.hitProp = cudaAccessPropertyPersisting;
                attr.accessPolicyWindow.missProp = cudaAccessPropertyStreaming;
                cudaStreamSetAttribute((cudaStream_t)0,
                                       cudaStreamAttributeAccessPolicyWindow, &attr);
                cudaStreamSetAttribute(sB,
                                       cudaStreamAttributeAccessPolicyWindow, &attr);
            }
        }
        init_done = true;
    }

    /* fork: CSR build on stream B, overlapped with split + GEMM on stream 0 */
    cudaEventRecord(evFork, 0);
    cudaStreamWaitEvent(sB, evFork, 0);

    zero_cnt_kernel<<<(N_NODES + 255) / 256, 256, 0, sB>>>();
    count_kernel<<<(N_EDGES + 255) / 256, 256, 0, sB>>>(dst);
    scan1_kernel<<<SCAN_NBLK, 1024, 0, sB>>>();
    scan2_kernel<<<1, 32, 0, sB>>>();
    scan3_kernel<<<(N_NODES + 255) / 256, 256, 0, sB>>>();
    scatter_kernel<<<(N_EDGES + 255) / 256, 256, 0, sB>>>(src, dst);
    cudaEventRecord(evJoin, sB);

    split_xw_kernel<<<(unsigned)(((size_t)N_PAD * IN_DIM / 4 + 255) / 256), 256>>>(x, W1);
    gemm_mma_kernel<<<dim3(F1 / 128, N_PAD / 128), 256, GEMM_SMEM>>>(aS1, aD1);

    /* join: gat1 needs both the GEMM outputs and the CSR */
    cudaStreamWaitEvent(0, evJoin, 0);

    gat1_fused<<<(N_NODES * 32 + 255) / 256, 256>>>(b1, W2, aS2, aD2);
    gat2_fused<<<(N_NODES * 32 + 255) / 256, 256>>>(out, b2);
}

// round 13
// speedup vs baseline: 1.0504x; 1.0504x over previous
#include <cuda_runtime.h>
#include <cuda_bf16.h>
#include <math.h>
#include <stdint.h>

#define N_NODES 50000
#define N_PAD   50048            /* 391 * 128 */
#define N_EDGES 800000
#define IN_DIM  384
#define HID     128
#define HEADS   4
#define OUT_DIM 5
#define F1      (HEADS * HID)    /* 512 */
#define EPS     1e-16f
#define NEG_SLOPE 0.2f
#define KC      64               /* K per chunk */
#define NCHUNK  18               /* 3 terms * 384/64 */
#define NEG_INF __int_as_float(0xff800000)
#define SCAN_NBLK ((N_NODES + 1023) / 1024)   /* 49 */

/* ---------------- scratch (device globals; no allocations allowed) -------- */
__device__ float g_h1  [(size_t)N_NODES * F1];     /* 102.4MB */
__device__ float g_alS1[N_NODES * HEADS];
__device__ float g_alD1[N_NODES * HEADS];
__device__ float g_h2p [N_NODES * 8];              /* padded h2 [N,8] */
__device__ float g_alS2[N_NODES];
__device__ float g_alD2[N_NODES];
/* CSR by destination */
__device__ int g_cnt   [N_NODES];
__device__ int g_rowptr[N_NODES + 1];
__device__ int g_cursor[N_NODES];
__device__ int g_ssrc  [N_EDGES];
__device__ int g_bsum  [SCAN_NBLK];
/* bf16 split operands for tensor-core GEMM1 */
__device__ __nv_bfloat16 g_xhi[(size_t)N_PAD * IN_DIM];
__device__ __nv_bfloat16 g_xlo[(size_t)N_PAD * IN_DIM];
__device__ __nv_bfloat16 g_wthi[(size_t)F1 * IN_DIM];   /* W1^T [512 x 384] */
__device__ __nv_bfloat16 g_wtlo[(size_t)F1 * IN_DIM];

/* ---------------- helpers ------------------------------------------------- */
__device__ __forceinline__ uint32_t smem_u32(const void* p) {
    uint32_t a;
    asm("{ .reg .u64 t; cvta.to.shared.u64 t, %1; cvt.u32.u64 %0, t; }"
        : "=r"(a) : "l"(p));
    return a;
}
__device__ __forceinline__ float leaky(float v) {
    return v > 0.0f ? v : NEG_SLOPE * v;
}
__device__ __forceinline__ void ldsm_x4(uint32_t* r, uint32_t addr) {
    asm volatile("ldmatrix.sync.aligned.m8n8.x4.shared.b16 {%0,%1,%2,%3}, [%4];"
                 : "=r"(r[0]), "=r"(r[1]), "=r"(r[2]), "=r"(r[3]) : "r"(addr));
}
__device__ __forceinline__ void mma_bf16(float* c, const uint32_t* a,
                                         const uint32_t* b) {
    asm volatile("mma.sync.aligned.m16n8k16.row.col.f32.bf16.bf16.f32 "
                 "{%0,%1,%2,%3}, {%4,%5,%6,%7}, {%8,%9}, {%0,%1,%2,%3};"
                 : "+f"(c[0]), "+f"(c[1]), "+f"(c[2]), "+f"(c[3])
                 : "r"(a[0]), "r"(a[1]), "r"(a[2]), "r"(a[3]),
                   "r"(b[0]), "r"(b[1]));
}
__device__ __forceinline__ void cp16(uint32_t saddr, const void* gaddr) {
    asm volatile("cp.async.cg.shared.global [%0], [%1], 16;"
                 :: "r"(saddr), "l"(gaddr));
}
#define CP_COMMIT() asm volatile("cp.async.commit_group;")
#define CP_WAIT0()  asm volatile("cp.async.wait_group 0;")
#define CP_WAIT1()  asm volatile("cp.async.wait_group 1;")

/* ---------------- split_x + split_w + init (fused) ------------------------- */
__global__ void split_xw_kernel(const float* __restrict__ x,
                                const float* __restrict__ W1) {
    size_t tid = (size_t)blockIdx.x * blockDim.x + threadIdx.x;
    if (tid < N_NODES * HEADS) { g_alS1[tid] = 0.0f; g_alD1[tid] = 0.0f; }

    /* W1^T split (196608 elements, done by the first threads) */
    if (tid < (size_t)F1 * IN_DIM) {
        int n = (int)(tid / IN_DIM), k = (int)(tid - (size_t)n * IN_DIM);
        float v = W1[(size_t)k * F1 + n];
        __nv_bfloat16 hi = __float2bfloat16(v);
        g_wthi[tid] = hi;
        g_wtlo[tid] = __float2bfloat16(v - __bfloat162float(hi));
    }

    size_t t = tid * 4;
    if (t >= (size_t)N_PAD * IN_DIM) return;
    float4 v = (t < (size_t)N_NODES * IN_DIM) ? *(const float4*)(x + t)
                                              : make_float4(0.f, 0.f, 0.f, 0.f);
    float vv[4] = {v.x, v.y, v.z, v.w};
    __nv_bfloat16 hi[4], lo[4];
#pragma unroll
    for (int i = 0; i < 4; i++) {
        hi[i] = __float2bfloat16(vv[i]);
        lo[i] = __float2bfloat16(vv[i] - __bfloat162float(hi[i]));
    }
    *(uint2*)(g_xhi + t) = *(uint2*)hi;
    *(uint2*)(g_xlo + t) = *(uint2*)lo;
}

/* ---------------- CSR build (stream B) ------------------------------------- */
__global__ void zero_cnt_kernel() {
    int t = blockIdx.x * blockDim.x + threadIdx.x;
    if (t < N_NODES) g_cnt[t] = 0;
}
__global__ void count_kernel(const int* __restrict__ dst) {
    int e = blockIdx.x * blockDim.x + threadIdx.x;
    if (e < N_EDGES) atomicAdd(&g_cnt[dst[e]], 1);
}
__global__ __launch_bounds__(1024)
void scan1_kernel() {                 /* per-block Hillis-Steele */
    __shared__ int s[1024];
    const int t = threadIdx.x;
    const int g = blockIdx.x * 1024 + t;
    const int v = (g < N_NODES) ? g_cnt[g] : 0;
    s[t] = v;
    __syncthreads();
#pragma unroll
    for (int off = 1; off < 1024; off <<= 1) {
        int x = (t >= off) ? s[t - off] : 0;
        __syncthreads();
        s[t] += x;
        __syncthreads();
    }
    if (g < N_NODES) g_rowptr[g] = s[t] - v;     /* exclusive partial */
    if (t == 1023) g_bsum[blockIdx.x] = s[1023];
}
__global__ void scan2_kernel() {      /* warp-parallel scan of 49 block sums */
    const int t = threadIdx.x;        /* 64 threads, 2 warps */
    __shared__ int s[64];
    int v = (t < SCAN_NBLK) ? g_bsum[t] : 0;
    s[t] = v;
    __syncthreads();
    for (int off = 1; off < 64; off <<= 1) {
        int x = (t >= off) ? s[t - off] : 0;
        __syncthreads();
        s[t] += x;
        __syncthreads();
    }
    if (t < SCAN_NBLK) g_bsum[t] = s[t] - v;     /* exclusive */
    if (t == SCAN_NBLK - 1) g_rowptr[N_NODES] = s[t];
}
__global__ void scan3_kernel() {      /* add block offsets, fill cursor */
    int g = blockIdx.x * blockDim.x + threadIdx.x;
    if (g < N_NODES) {
        int v = g_rowptr[g] + g_bsum[g >> 10];
        g_rowptr[g] = v;
        g_cursor[g] = v;
    }
}
__global__ void scatter_kernel(const int* __restrict__ src,
                               const int* __restrict__ dst) {
    int e = blockIdx.x * blockDim.x + threadIdx.x;
    if (e >= N_EDGES) return;
    int p = atomicAdd(&g_cursor[dst[e]], 1);
    g_ssrc[p] = src[e];
}

/* ------- GEMM1 via mma.sync bf16x3, cp.async 3-stage pipeline -------------- */
#define GEMM_SMEM (3 * 32768)

__global__ __launch_bounds__(256, 2)
void gemm_mma_kernel(const float* __restrict__ aSrc,
                     const float* __restrict__ aDst) {
    extern __shared__ char smem[];
    const uint32_t sb = smem_u32(smem);
    const int tid = threadIdx.x, lane = tid & 31, wid = tid >> 5;
    const int wM = (wid & 3) * 32, wN = (wid >> 2) * 64;
    const size_t bm = (size_t)blockIdx.y * 128;
    const int bn0 = blockIdx.x * 128;

    float acc[2][8][4];
#pragma unroll
    for (int i = 0; i < 2; i++)
#pragma unroll
        for (int j = 0; j < 8; j++)
#pragma unroll
            for (int q = 0; q < 4; q++) acc[i][j][q] = 0.0f;

    auto issue = [&](int ch, int buf) {
        const int term = ch / 6, k0 = (ch % 6) * KC;
        const __nv_bfloat16* Ag = (term < 2) ? g_xhi : g_xlo;
        const __nv_bfloat16* Bg = (term == 1) ? g_wtlo : g_wthi;
        const uint32_t base = sb + buf * 32768;
#pragma unroll
        for (int l = 0; l < 4; l++) {
            int i = tid + l * 256;
            int r = i >> 3, c = i & 7;
            uint32_t off = r * 128 + ((c ^ (r & 7)) << 4);
            cp16(base + off, Ag + (bm + r) * IN_DIM + k0 + c * 8);
            cp16(base + 16384 + off, Bg + (size_t)(bn0 + r) * IN_DIM + k0 + c * 8);
        }
        CP_COMMIT();
    };

    issue(0, 0);
    issue(1, 1);

    for (int ch = 0; ch < NCHUNK; ch++) {
        if (ch + 1 < NCHUNK) CP_WAIT1(); else CP_WAIT0();
        __syncthreads();
        if (ch + 2 < NCHUNK) issue(ch + 2, (ch + 2) % 3);
        const uint32_t sbA = sb + (ch % 3) * 32768;
        const uint32_t sbB = sbA + 16384;
#pragma unroll
        for (int k16 = 0; k16 < 4; k16++) {
            uint32_t a[2][4];
#pragma unroll
            for (int am = 0; am < 2; am++) {
                int r = wM + am * 16 + (lane & 15);
                int c = k16 * 2 + (lane >> 4);
                ldsm_x4(a[am], sbA + r * 128 + ((c ^ (r & 7)) << 4));
            }
#pragma unroll
            for (int bn2 = 0; bn2 < 4; bn2++) {
                int n = wN + bn2 * 16 + ((lane >> 4) << 3) + (lane & 7);
                int c = k16 * 2 + ((lane >> 3) & 1);
                uint32_t b[4];
                ldsm_x4(b, sbB + n * 128 + ((c ^ (n & 7)) << 4));
                mma_bf16(acc[0][bn2 * 2], a[0], b);
                mma_bf16(acc[1][bn2 * 2], a[1], b);
                mma_bf16(acc[0][bn2 * 2 + 1], a[0], b + 2);
                mma_bf16(acc[1][bn2 * 2 + 1], a[1], b + 2);
            }
        }
    }

    /* epilogue: write h1 + fused alpha1 partial dot products */
    const int qr = lane >> 2, qc = (lane & 3) * 2;
    const int hh = bn0 >> 7;
    float sA[4] = {0, 0, 0, 0}, sD[4] = {0, 0, 0, 0};

#pragma unroll
    for (int am = 0; am < 2; am++) {
        size_t r0 = bm + wM + am * 16 + qr;
#pragma unroll
        for (int half = 0; half < 2; half++) {
            size_t rr = r0 + half * 8;
            if (rr < N_NODES) {
                float* dstp = g_h1 + rr * F1 + bn0 + wN + qc;
#pragma unroll
                for (int bn = 0; bn < 8; bn++) {
                    float v0 = acc[am][bn][half * 2];
                    float v1 = acc[am][bn][half * 2 + 1];
                    *(float2*)(dstp + bn * 8) = make_float2(v0, v1);
                    const int c0 = bn0 + wN + bn * 8 + qc;
                    sA[am * 2 + half] += v0 * __ldg(aSrc + c0) + v1 * __ldg(aSrc + c0 + 1);
                    sD[am * 2 + half] += v0 * __ldg(aDst + c0) + v1 * __ldg(aDst + c0 + 1);
                }
            }
        }
    }
#pragma unroll
    for (int i = 0; i < 4; i++) {
#pragma unroll
        for (int o = 1; o <= 2; o <<= 1) {
            sA[i] += __shfl_xor_sync(0xffffffffu, sA[i], o);
            sD[i] += __shfl_xor_sync(0xffffffffu, sD[i], o);
        }
    }
    if ((lane & 3) == 0) {
#pragma unroll
        for (int am = 0; am < 2; am++)
#pragma unroll
            for (int half = 0; half < 2; half++) {
                size_t rr = bm + wM + am * 16 + half * 8 + qr;
                if (rr < N_NODES) {
                    atomicAdd(&g_alS1[rr * HEADS + hh], sA[am * 2 + half]);
                    atomicAdd(&g_alD1[rr * HEADS + hh], sD[am * 2 + half]);
                }
            }
    }
}

/* -------- layer1 fused: one warp per dst, ALL 4 heads ---------------------- */
__global__ __launch_bounds__(256)
void gat1_fused(const float* __restrict__ b1, const float* __restrict__ W2,
                const float* __restrict__ a_s2, const float* __restrict__ a_d2) {
    const int d = (blockIdx.x * blockDim.x + threadIdx.x) >> 5;
    const int lane = threadIdx.x & 31;
    if (d >= N_NODES) return;
    const int rs = g_rowptr[d];
    const int deg = g_rowptr[d + 1] - rs;
    const float4 aD4 = *(const float4*)&g_alD1[d * HEADS];
    const float aD[4] = {aD4.x, aD4.y, aD4.z, aD4.w};

    float m[4] = {NEG_INF, NEG_INF, NEG_INF, NEG_INF};
    float den[4] = {0, 0, 0, 0};
    float acc[4][4] = {};

    for (int base = 0; base < deg; base += 32) {
        const bool act = base + lane < deg;
        int s = 0;
        float lg[4] = {NEG_INF, NEG_INF, NEG_INF, NEG_INF};
        if (act) {
            s = g_ssrc[rs + base + lane];
            float4 a4 = *(const float4*)&g_alS1[s * HEADS];
            lg[0] = leaky(a4.x + aD[0]);
            lg[1] = leaky(a4.y + aD[1]);
            lg[2] = leaky(a4.z + aD[2]);
            lg[3] = leaky(a4.w + aD[3]);
        }
        float ex[4];
#pragma unroll
        for (int h = 0; h < 4; h++) {
            float bmx = lg[h];
#pragma unroll
            for (int o = 16; o; o >>= 1)
                bmx = fmaxf(bmx, __shfl_xor_sync(0xffffffffu, bmx, o));
            const float mnew = fmaxf(m[h], bmx);
            const float sc = __expf(m[h] - mnew);
            den[h] *= sc;
            acc[h][0] *= sc; acc[h][1] *= sc; acc[h][2] *= sc; acc[h][3] *= sc;
            ex[h] = act ? __expf(lg[h] - mnew) : 0.f;
            den[h] += ex[h];
            m[h] = mnew;
        }
        const int lim = min(32, deg - base);
        for (int jj = 0; jj < lim; jj++) {
            const int sj = __shfl_sync(0xffffffffu, s, jj);
            const float w0 = __shfl_sync(0xffffffffu, ex[0], jj);
            const float w1 = __shfl_sync(0xffffffffu, ex[1], jj);
            const float w2 = __shfl_sync(0xffffffffu, ex[2], jj);
            const float w3 = __shfl_sync(0xffffffffu, ex[3], jj);
            const float* row = g_h1 + (size_t)sj * F1 + lane * 4;
            const float4 v0 = *(const float4*)(row);
            const float4 v1 = *(const float4*)(row + HID);
            const float4 v2 = *(const float4*)(row + 2 * HID);
            const float4 v3 = *(const float4*)(row + 3 * HID);
            acc[0][0] += w0 * v0.x; acc[0][1] += w0 * v0.y;
            acc[0][2] += w0 * v0.z; acc[0][3] += w0 * v0.w;
            acc[1][0] += w1 * v1.x; acc[1][1] += w1 * v1.y;
            acc[1][2] += w1 * v1.z; acc[1][3] += w1 * v1.w;
            acc[2][0] += w2 * v2.x; acc[2][1] += w2 * v2.y;
            acc[2][2] += w2 * v2.z; acc[2][3] += w2 * v2.w;
            acc[3][0] += w3 * v3.x; acc[3][1] += w3 * v3.y;
            acc[3][2] += w3 * v3.z; acc[3][3] += w3 * v3.w;
        }
    }
    float inv[4];
#pragma unroll
    for (int h = 0; h < 4; h++) {
        float dn = den[h];
#pragma unroll
        for (int o = 16; o; o >>= 1)
            dn += __shfl_xor_sync(0xffffffffu, dn, o);
        inv[h] = 1.0f / (dn + EPS);
    }

    float p[OUT_DIM] = {0, 0, 0, 0, 0};
#pragma unroll
    for (int h = 0; h < 4; h++) {
#pragma unroll
        for (int q = 0; q < 4; q++) {
            const int c = h * HID + lane * 4 + q;
            float val = acc[h][q] * inv[h] + b1[c];
            val = val > 0.0f ? val : expm1f(val);
            const float* wr = W2 + c * OUT_DIM;
#pragma unroll
            for (int k = 0; k < OUT_DIM; k++) p[k] += val * wr[k];
        }
    }
#pragma unroll
    for (int k = 0; k < OUT_DIM; k++) {
#pragma unroll
        for (int o = 16; o; o >>= 1)
            p[k] += __shfl_xor_sync(0xffffffffu, p[k], o);
    }
    if (lane == 0) {
        float as = 0.f, ad = 0.f;
#pragma unroll
        for (int k = 0; k < OUT_DIM; k++) {
            g_h2p[d * 8 + k] = p[k];
            as += p[k] * a_s2[k];
            ad += p[k] * a_d2[k];
        }
        g_alS2[d] = as;
        g_alD2[d] = ad;
    }
}

/* -------- layer2 fused: per-lane online softmax, direct store -------------- */
__global__ __launch_bounds__(256)
void gat2_fused(float* __restrict__ dout, const float* __restrict__ b2) {
    const int d = (blockIdx.x * blockDim.x + threadIdx.x) >> 5;
    const int lane = threadIdx.x & 31;
    if (d >= N_NODES) return;
    const int rs = g_rowptr[d];
    const int deg = g_rowptr[d + 1] - rs;
    if (deg == 0) {
        if (lane == 0) {
#pragma unroll
            for (int k = 0; k < OUT_DIM; k++)
                dout[d * OUT_DIM + k] = b2[k];
        }
        return;
    }
    const float aD = g_alD2[d];

    float m = NEG_INF, den = 0.f;
    float acc[OUT_DIM] = {0, 0, 0, 0, 0};
    for (int j = lane; j < deg; j += 32) {
        int s = g_ssrc[rs + j];
        float lg = leaky(g_alS2[s] + aD);
        float mnew = fmaxf(m, lg);
        float sc = __expf(m - mnew);
        float ex = __expf(lg - mnew);
        den = den * sc + ex;
#pragma unroll
        for (int k = 0; k < OUT_DIM; k++)
            acc[k] = acc[k] * sc + ex * g_h2p[s * 8 + k];
        m = mnew;
    }
    float M = m;
#pragma unroll
    for (int o = 16; o; o >>= 1)
        M = fmaxf(M, __shfl_xor_sync(0xffffffffu, M, o));
    float sc = __expf(m - M);
    den *= sc;
#pragma unroll
    for (int k = 0; k < OUT_DIM; k++) acc[k] *= sc;
#pragma unroll
    for (int o = 16; o; o >>= 1) {
        den += __shfl_xor_sync(0xffffffffu, den, o);
#pragma unroll
        for (int k = 0; k < OUT_DIM; k++)
            acc[k] += __shfl_xor_sync(0xffffffffu, acc[k], o);
    }
    if (lane == 0) {
        const float inv = 1.0f / (den + EPS);
#pragma unroll
        for (int k = 0; k < OUT_DIM; k++)
            dout[d * OUT_DIM + k] = acc[k] * inv + b2[k];
    }
}

/* ---------------- launch --------------------------------------------------- */
extern "C" void kernel_launch(void* const* d_in, const int* in_sizes, int n_in,
                              void* d_out, int out_size) {
    const float* x   = (const float*)d_in[0];
    const int*   ei  = (const int*)  d_in[1];
    const float* W1  = (const float*)d_in[2];
    const float* aS1 = (const float*)d_in[3];
    const float* aD1 = (const float*)d_in[4];
    const float* b1  = (const float*)d_in[5];
    const float* W2  = (const float*)d_in[6];
    const float* aS2 = (const float*)d_in[7];
    const float* aD2 = (const float*)d_in[8];
    const float* b2  = (const float*)d_in[9];
    float*       out = (float*)d_out;

    const int* src = ei;
    const int* dst = ei + N_EDGES;

    static bool init_done = false;
    static cudaStream_t sB;
    static cudaEvent_t evFork, evJoin;
    if (!init_done) {
        cudaFuncSetAttribute(gemm_mma_kernel,
                             cudaFuncAttributeMaxDynamicSharedMemorySize, GEMM_SMEM);
        cudaStreamCreateWithFlags(&sB, cudaStreamNonBlocking);
        cudaEventCreateWithFlags(&evFork, cudaEventDisableTiming);
        cudaEventCreateWithFlags(&evJoin, cudaEventDisableTiming);
        init_done = true;
    }

    /* fork: CSR build on stream B, overlapped with split + GEMM on stream 0 */
    cudaEventRecord(evFork, 0);
    cudaStreamWaitEvent(sB, evFork, 0);

    zero_cnt_kernel<<<(N_NODES + 255) / 256, 256, 0, sB>>>();
    count_kernel<<<(N_EDGES + 255) / 256, 256, 0, sB>>>(dst);
    scan1_kernel<<<SCAN_NBLK, 1024, 0, sB>>>();
    scan2_kernel<<<1, 64, 0, sB>>>();
    scan3_kernel<<<(N_NODES + 255) / 256, 256, 0, sB>>>();
    scatter_kernel<<<(N_EDGES + 255) / 256, 256, 0, sB>>>(src, dst);
    cudaEventRecord(evJoin, sB);

    split_xw_kernel<<<(unsigned)(((size_t)N_PAD * IN_DIM / 4 + 255) / 256), 256>>>(x, W1);
    gemm_mma_kernel<<<dim3(F1 / 128, N_PAD / 128), 256, GEMM_SMEM>>>(aS1, aD1);

    /* join: gat1 needs both the GEMM outputs and the CSR */
    cudaStreamWaitEvent(0, evJoin, 0);

    gat1_fused<<<(N_NODES * 32 + 255) / 256, 256>>>(b1, W2, aS2, aD2);
    gat2_fused<<<(N_NODES * 32 + 255) / 256, 256>>>(out, b2);
}